// round 11
// baseline (speedup 1.0000x reference)
#include <cuda_runtime.h>
#include <math.h>

#define NN      8192
#define KZ      20
#define PDIM    20
#define NVZ     64
#define NUMPROT 20
#define FZ      256
#define NFEAT   2000
#define NDIST   100

// output layout: tuple members concatenated, float32
#define OFF_POS (NN*(FZ+NVZ))
#define OFF_NP  (OFF_POS + NN*3)
#define OFF_ND  (OFF_NP  + NN*KZ*3)
#define OFF_EI  (OFF_ND  + NN*KZ*PDIM)
#define OFF_FEI (OFF_EI  + NN*KZ)

typedef unsigned long long u64;

// device scratch (allocation-free rule -> static globals)
__device__ float4 g_pos4[NN];
__device__ float4 g_ncac[NN*3];
__device__ int    g_edge[NN*KZ];
__device__ float  g_wt[NFEAT*NVZ];
__device__ float  g_enc[NN*NFEAT];
__device__ float  g_freq[PDIM/2];
__device__ int    g_mask_kind;

__device__ __forceinline__ u64 ffma2(u64 a, u64 b, u64 c) {
    u64 d;
    asm("fma.rn.f32x2 %0, %1, %2, %3;" : "=l"(d) : "l"(a), "l"(b), "l"(c));
    return d;
}
__device__ __forceinline__ u64 pack2(float x, float y) {
    u64 r;
    asm("mov.b64 %0, {%1, %2};" : "=l"(r) : "f"(x), "f"(y));
    return r;
}
__device__ __forceinline__ void unpack2(u64 v, float& x, float& y) {
    asm("mov.b64 {%0, %1}, %2;" : "=f"(x), "=f"(y) : "l"(v));
}

// ---------------------------------------------------------------------------
// FMA-pipe sincos (abs err < 4e-6 for |x| < 25)
// ---------------------------------------------------------------------------
__device__ __forceinline__ void sincos_poly(float x, float& so, float& co) {
    float q = rintf(x * 0.6366197723675814f);
    int iq = (int)q;
    float r = fmaf(-q, 1.57079637050628662109375f, x);
    r = fmaf(-q, -4.37113900018624283e-8f, r);
    float r2 = r * r;
    float ps = fmaf(-1.9841270114e-4f, r2, 8.3333337680e-3f);
    ps = fmaf(ps, r2, -1.6666667163e-1f);
    float sinr = fmaf(ps * r2, r, r);
    float pc = fmaf(-1.3888889225e-3f, r2, 4.1666667908e-2f);
    pc = fmaf(pc, r2, -0.5f);
    float cosr = fmaf(pc, r2, 1.0f);
    int qq = iq & 3;
    float s_ = (qq & 1) ? cosr : sinr;
    float c_ = (qq & 1) ? sinr : cosr;
    if (qq == 1 || qq == 2) c_ = -c_;
    if (qq >= 2) s_ = -s_;
    so = s_; co = c_;
}

// ---------------------------------------------------------------------------
// Classify prot_mask storage: 0=int32(0/1 words), 1=uint8, 2=float32.
// ---------------------------------------------------------------------------
__global__ void detect_kernel(const unsigned int* __restrict__ m) {
    __shared__ int red[256];
    int t = threadIdx.x;
    int code = 0;
    for (int i = t; i < 2048; i += 256) {
        unsigned w = m[i];
        if (w == 0x3F800000u) code = 2;
        else if (w != 0u && w != 1u) code = max(code, 1);
    }
    red[t] = code; __syncthreads();
    for (int s = 128; s > 0; s >>= 1) {
        if (t < s) red[t] = max(red[t], red[t+s]);
        __syncthreads();
    }
    if (t == 0) g_mask_kind = red[0];
    if (t < PDIM/2) g_freq[t] = (float)exp(-0.39120230054281463 * (double)t);
}

// ne_weight (64,2000) -> g_wt (2000,64)
__global__ void wt_kernel(const float* __restrict__ w) {
    int idx = blockIdx.x*256 + threadIdx.x;
    if (idx >= NVZ*NFEAT) return;
    int o = idx / NFEAT, f = idx - o*NFEAT;
    g_wt[f*NVZ + o] = w[idx];
}

// per-node: pos4 (pos + |p|^2, plain asc rounding), ncac atoms, positions out
__global__ void setup_kernel(const float* __restrict__ aff,
                             const float* __restrict__ lit,
                             const void*  __restrict__ maskp,
                             float* __restrict__ out) {
    int i = blockIdx.x*256 + threadIdx.x;
    if (i >= NN) return;
    const float* A = aff + i*12;
    float r0=A[0], r1=A[1], r2=A[2],  tx=A[3];
    float r3=A[4], r4=A[5], r5=A[6],  ty=A[7];
    float r6=A[8], r7=A[9], r8=A[10], tz=A[11];
    float n2 = __fadd_rn(__fadd_rn(__fmul_rn(tx,tx), __fmul_rn(ty,ty)),
                         __fmul_rn(tz,tz));
    g_pos4[i] = make_float4(tx,ty,tz,n2);
    out[OFF_POS+i*3+0]=tx; out[OFF_POS+i*3+1]=ty; out[OFF_POS+i*3+2]=tz;

    int kind = g_mask_kind;
    bool mk;
    if (kind == 1)      mk = ((const unsigned char*)maskp)[i] != 0;
    else if (kind == 2) mk = ((const float*)maskp)[i] != 0.0f;
    else                mk = ((const int*)maskp)[i] != 0;
    const float* L = lit + (mk ? 0 : NUMPROT)*9;
    #pragma unroll
    for (int a = 0; a < 3; a++) {
        float lx=L[a*3+0], ly=L[a*3+1], lz=L[a*3+2];
        float px = fmaf(r0,lx, fmaf(r1,ly, r2*lz)) + tx;
        float py = fmaf(r3,lx, fmaf(r4,ly, r5*lz)) + ty;
        float pz = fmaf(r6,lx, fmaf(r7,ly, r8*lz)) + tz;
        g_ncac[i*3+a] = make_float4(px,py,pz,0.f);
    }
}

// ---------------------------------------------------------------------------
// kNN: warp handles FOUR queries; candidate LDS amortized 4x. Four
// lane-distributed top-20 lists, lexicographic (d2, index) order.
// d2 bits FROZEN: dot = fma(z,z', fma(y,y', rn(x*x')));
//                 d2  = rn(n2i + fma(-2,dot,n2j))
// ---------------------------------------------------------------------------
#define KTILE 2048
__global__ void __launch_bounds__(256) knn_kernel(float* __restrict__ out) {
    __shared__ float4 tile[KTILE];
    const unsigned FULL = 0xffffffffu;
    int warp = threadIdx.x >> 5;
    int lane = threadIdx.x & 31;
    int q0 = (blockIdx.x*8 + warp)*4;
    float4 P0 = g_pos4[q0+0];
    float4 P1 = g_pos4[q0+1];
    float4 P2 = g_pos4[q0+2];
    float4 P3 = g_pos4[q0+3];
    const float INF = __int_as_float(0x7f800000);
    float dist[4]; int idx[4];
    float thrd[4]; int thri[4];
    #pragma unroll
    for (int t = 0; t < 4; t++) {
        dist[t] = INF; idx[t] = 0x7FFFFFFF;
        thrd[t] = INF; thri[t] = 0x7FFFFFFF;
    }

    for (int t0 = 0; t0 < NN; t0 += KTILE) {
        __syncthreads();
        for (int i = threadIdx.x; i < KTILE; i += 256) tile[i] = g_pos4[t0+i];
        __syncthreads();
        #pragma unroll 2
        for (int b = 0; b < KTILE; b += 32) {
            int j = t0 + b + lane;
            float4 c = tile[b + lane];
            float m2 = __fmaf_rn(-2.0f, 1.0f, 0.0f); (void)m2;
            float dot0 = __fmaf_rn(P0.z, c.z, __fmaf_rn(P0.y, c.y, __fmul_rn(P0.x, c.x)));
            float dot1 = __fmaf_rn(P1.z, c.z, __fmaf_rn(P1.y, c.y, __fmul_rn(P1.x, c.x)));
            float dot2 = __fmaf_rn(P2.z, c.z, __fmaf_rn(P2.y, c.y, __fmul_rn(P2.x, c.x)));
            float dot3 = __fmaf_rn(P3.z, c.z, __fmaf_rn(P3.y, c.y, __fmul_rn(P3.x, c.x)));
            float d2v[4];
            d2v[0] = __fadd_rn(P0.w, __fmaf_rn(-2.0f, dot0, c.w));
            d2v[1] = __fadd_rn(P1.w, __fmaf_rn(-2.0f, dot1, c.w));
            d2v[2] = __fadd_rn(P2.w, __fmaf_rn(-2.0f, dot2, c.w));
            d2v[3] = __fadd_rn(P3.w, __fmaf_rn(-2.0f, dot3, c.w));
            unsigned bals[4];
            #pragma unroll
            for (int qq = 0; qq < 4; qq++) {
                bool qual = (j != q0+qq) &&
                            (d2v[qq] < thrd[qq] ||
                             (d2v[qq] == thrd[qq] && j < thri[qq]));
                bals[qq] = __ballot_sync(FULL, qual);
            }
            if (bals[0] | bals[1] | bals[2] | bals[3]) {
                #pragma unroll
                for (int qq = 0; qq < 4; qq++) {
                    unsigned bal = bals[qq];
                    if (!bal) continue;
                    do {
                        int src = __ffs(bal) - 1; bal &= bal - 1;
                        float cd = __shfl_sync(FULL, d2v[qq], src);
                        int   ci = t0 + b + src;
                        unsigned mlt = __ballot_sync(FULL,
                            (dist[qq] < cd) || (dist[qq] == cd && idx[qq] < ci)) & 0xFFFFFu;
                        int p = __popc(mlt);
                        if (p < 20) {
                            float nd = __shfl_up_sync(FULL, dist[qq], 1);
                            int   ni = __shfl_up_sync(FULL, idx[qq], 1);
                            if (lane >= p && lane < 20) {
                                dist[qq] = (lane == p) ? cd : nd;
                                idx[qq]  = (lane == p) ? ci : ni;
                            }
                        }
                    } while (bal);
                    thrd[qq] = __shfl_sync(FULL, dist[qq], 19);
                    thri[qq] = __shfl_sync(FULL, idx[qq], 19);
                }
            }
        }
    }
    if (lane < KZ) {
        #pragma unroll
        for (int qq = 0; qq < 4; qq++) {
            int q = q0 + qq;
            g_edge[q*KZ+lane] = idx[qq];
            out[OFF_EI  + q*KZ + lane] = (float)idx[qq];
            out[OFF_FEI + q*KZ + lane] = (float)idx[qq];
            out[OFF_FEI + NN*KZ + q*KZ + lane] = (float)q;
        }
    }
}

// ---------------------------------------------------------------------------
// Merged per-node geometry + encoding. 128 threads per node:
// threads 0..19 do edge geometry (writes + backbone distances into smem),
// then all 128 compute the 1000 sincos pairs of enc.
// ---------------------------------------------------------------------------
__global__ void __launch_bounds__(128) geom_enc_kernel(const float* __restrict__ aff,
                                                       float* __restrict__ out) {
    __shared__ float dl[NDIST];
    __shared__ float fl[PDIM/2];
    int n = blockIdx.x;
    int tid = threadIdx.x;
    if (tid < PDIM/2) fl[tid] = g_freq[tid];
    __syncthreads();

    if (tid < KZ) {
        int k = tid;
        const float* A = aff + n*12;
        float r0=A[0], r1=A[1], r2=A[2],  tx=A[3];
        float r3=A[4], r4=A[5], r5=A[6],  ty=A[7];
        float r6=A[8], r7=A[9], r8=A[10], tz=A[11];
        int j = g_edge[n*KZ+k];
        float4 nb = g_pos4[j];
        float vx = nb.x - tx, vy = nb.y - ty, vz = nb.z - tz;
        float ex = fmaf(r0,vx, fmaf(r3,vy, r6*vz));
        float ey = fmaf(r1,vx, fmaf(r4,vy, r7*vz));
        float ez = fmaf(r2,vx, fmaf(r5,vy, r8*vz));
        int eb = (n*KZ+k)*3;
        out[OFF_NP+eb+0]=ex; out[OFF_NP+eb+1]=ey; out[OFF_NP+eb+2]=ez;
        float nrm = sqrtf(fmaf(ex,ex, fmaf(ey,ey, ez*ez)));
        int db = (n*KZ+k)*PDIM;
        #pragma unroll
        for (int t = 0; t < PDIM/2; t++) {
            float sv, cv;
            sincos_poly(nrm * fl[t], sv, cv);
            out[OFF_ND+db+t]    = sv;
            out[OFF_ND+db+10+t] = cv;
        }
        float4 ca = g_ncac[n*3+1], np = g_ncac[n*3+0], cp = g_ncac[n*3+2];
        #pragma unroll
        for (int a = 0; a < 3; a++) {
            float4 p = g_ncac[j*3+a];
            float dx=p.x-ca.x, dy=p.y-ca.y, dz=p.z-ca.z;
            dl[k*3 + a] = sqrtf(fmaf(dx,dx, fmaf(dy,dy, dz*dz)));
        }
        {
            float4 p = g_ncac[j*3+2];
            float dx=p.x-np.x, dy=p.y-np.y, dz=p.z-np.z;
            dl[60 + k] = sqrtf(fmaf(dx,dx, fmaf(dy,dy, dz*dz)));
            float4 p2 = g_ncac[j*3+0];
            float ex2=p2.x-cp.x, ey2=p2.y-cp.y, ez2=p2.z-cp.z;
            dl[80 + k] = sqrtf(fmaf(ex2,ex2, fmaf(ey2,ey2, ez2*ez2)));
        }
    }
    __syncthreads();

    for (int f = tid; f < NDIST*(PDIM/2); f += 128) {
        int d = f / 10;
        int t = f - d*10;
        float sv, cv;
        sincos_poly(dl[d] * fl[t], sv, cv);
        g_enc[n*NFEAT + d*20 + t]      = sv;
        g_enc[n*NFEAT + d*20 + 10 + t] = cv;
    }
}

// ---------------------------------------------------------------------------
// GEMM (f32x2 packed FMA) + fused x-copy.
// C(8192x64) = g_enc(8192x2000) @ g_wt(2000x64); per-element fp32 fma
// sequence identical to scalar version (k ascending) -> bitwise same.
// ---------------------------------------------------------------------------
#define BK 16
__global__ void __launch_bounds__(256) gemm_kernel(const float* __restrict__ x,
                                                   float* __restrict__ out) {
    __shared__ float As[BK][68];
    __shared__ float Bs[BK][64];
    int tid = threadIdx.x;
    int tx = tid & 15, ty = tid >> 4;
    int m0 = blockIdx.x * 64;

    // fused copyx: rows m0..m0+63, 256 floats each (4096 float4 / 256 thr)
    {
        const float4* xs = (const float4*)(x) + (size_t)m0*64;
        float4* od = (float4*)out;
        #pragma unroll
        for (int i = 0; i < 16; i++) {
            int e = tid + i*256;          // 0..4095
            int r = e >> 6, c = e & 63;
            od[(size_t)(m0+r)*80 + c] = xs[e];
        }
    }

    u64 acc[4][2];
    #pragma unroll
    for (int a = 0; a < 4; a++) { acc[a][0] = pack2(0.f,0.f); acc[a][1] = pack2(0.f,0.f); }

    const float* Ag = g_enc + (size_t)m0 * NFEAT;
    for (int kt = 0; kt < NFEAT; kt += BK) {
        #pragma unroll
        for (int i = 0; i < 4; i++) {
            int e = tid + i*256;
            int m = e >> 4, kk = e & 15;
            As[kk][m] = Ag[m*NFEAT + kt + kk];
        }
        #pragma unroll
        for (int i = 0; i < 4; i++) {
            int e = tid + i*256;
            int kk = e >> 6, nn = e & 63;
            Bs[kk][nn] = g_wt[(kt+kk)*NVZ + nn];
        }
        __syncthreads();
        #pragma unroll
        for (int kk = 0; kk < BK; kk++) {
            float4 a = *(const float4*)&As[kk][ty*4];
            const u64* bp = (const u64*)&Bs[kk][tx*4];
            u64 b01 = bp[0], b23 = bp[1];
            float av[4] = {a.x,a.y,a.z,a.w};
            #pragma unroll
            for (int i = 0; i < 4; i++) {
                u64 ai = pack2(av[i], av[i]);
                acc[i][0] = ffma2(ai, b01, acc[i][0]);
                acc[i][1] = ffma2(ai, b23, acc[i][1]);
            }
        }
        __syncthreads();
    }
    #pragma unroll
    for (int i = 0; i < 4; i++) {
        int m = m0 + ty*4 + i;
        float c0,c1,c2,c3;
        unpack2(acc[i][0], c0, c1);
        unpack2(acc[i][1], c2, c3);
        float* od = out + (size_t)m*(FZ+NVZ) + FZ + tx*4;
        od[0]=c0; od[1]=c1; od[2]=c2; od[3]=c3;
    }
}

extern "C" void kernel_launch(void* const* d_in, const int* in_sizes, int n_in,
                              void* d_out, int out_size) {
    const float* x    = (const float*)d_in[0];
    const float* aff  = (const float*)d_in[1];
    const float* nw   = (const float*)d_in[2];
    const float* lit  = (const float*)d_in[3];
    const void*  mask = d_in[4];
    float* out = (float*)d_out;

    detect_kernel<<<1, 256>>>((const unsigned int*)mask);
    wt_kernel<<<(NVZ*NFEAT + 255)/256, 256>>>(nw);
    setup_kernel<<<(NN+255)/256, 256>>>(aff, lit, mask, out);
    knn_kernel<<<NN/32, 256>>>(out);
    geom_enc_kernel<<<NN, 128>>>(aff, out);
    gemm_kernel<<<NN/64, 256>>>(x, out);
}

// round 12
// speedup vs baseline: 1.1395x; 1.1395x over previous
#include <cuda_runtime.h>
#include <math.h>

#define NN      8192
#define KZ      20
#define PDIM    20
#define NVZ     64
#define NUMPROT 20
#define FZ      256
#define NFEAT   2000
#define NDIST   100

// output layout: tuple members concatenated, float32
#define OFF_POS (NN*(FZ+NVZ))
#define OFF_NP  (OFF_POS + NN*3)
#define OFF_ND  (OFF_NP  + NN*KZ*3)
#define OFF_EI  (OFF_ND  + NN*KZ*PDIM)
#define OFF_FEI (OFF_EI  + NN*KZ)

typedef unsigned long long u64;

// device scratch (allocation-free rule -> static globals)
__device__ float4 g_pos4[NN];
__device__ float4 g_ncac[NN*3];
__device__ int    g_edge[NN*KZ];
__device__ float  g_wt[NFEAT*NVZ];
__device__ float  g_enc[NN*NFEAT];
__device__ float  g_freq[PDIM/2];
__device__ int    g_mask_kind;

__device__ __forceinline__ u64 ffma2(u64 a, u64 b, u64 c) {
    u64 d;
    asm("fma.rn.f32x2 %0, %1, %2, %3;" : "=l"(d) : "l"(a), "l"(b), "l"(c));
    return d;
}
__device__ __forceinline__ u64 pack2(float x, float y) {
    u64 r;
    asm("mov.b64 %0, {%1, %2};" : "=l"(r) : "f"(x), "f"(y));
    return r;
}
__device__ __forceinline__ void unpack2(u64 v, float& x, float& y) {
    asm("mov.b64 {%0, %1}, %2;" : "=f"(x), "=f"(y) : "l"(v));
}

// ---------------------------------------------------------------------------
// FMA-pipe sincos (abs err < 4e-6 for |x| < 25)
// ---------------------------------------------------------------------------
__device__ __forceinline__ void sincos_poly(float x, float& so, float& co) {
    float q = rintf(x * 0.6366197723675814f);
    int iq = (int)q;
    float r = fmaf(-q, 1.57079637050628662109375f, x);
    r = fmaf(-q, -4.37113900018624283e-8f, r);
    float r2 = r * r;
    float ps = fmaf(-1.9841270114e-4f, r2, 8.3333337680e-3f);
    ps = fmaf(ps, r2, -1.6666667163e-1f);
    float sinr = fmaf(ps * r2, r, r);
    float pc = fmaf(-1.3888889225e-3f, r2, 4.1666667908e-2f);
    pc = fmaf(pc, r2, -0.5f);
    float cosr = fmaf(pc, r2, 1.0f);
    int qq = iq & 3;
    float s_ = (qq & 1) ? cosr : sinr;
    float c_ = (qq & 1) ? sinr : cosr;
    if (qq == 1 || qq == 2) c_ = -c_;
    if (qq >= 2) s_ = -s_;
    so = s_; co = c_;
}

// ---------------------------------------------------------------------------
// Classify prot_mask storage: 0=int32(0/1 words), 1=uint8, 2=float32.
// ---------------------------------------------------------------------------
__global__ void detect_kernel(const unsigned int* __restrict__ m) {
    __shared__ int red[256];
    int t = threadIdx.x;
    int code = 0;
    for (int i = t; i < 2048; i += 256) {
        unsigned w = m[i];
        if (w == 0x3F800000u) code = 2;
        else if (w != 0u && w != 1u) code = max(code, 1);
    }
    red[t] = code; __syncthreads();
    for (int s = 128; s > 0; s >>= 1) {
        if (t < s) red[t] = max(red[t], red[t+s]);
        __syncthreads();
    }
    if (t == 0) g_mask_kind = red[0];
    if (t < PDIM/2) g_freq[t] = (float)exp(-0.39120230054281463 * (double)t);
}

// ne_weight (64,2000) -> g_wt (2000,64)
__global__ void wt_kernel(const float* __restrict__ w) {
    int idx = blockIdx.x*256 + threadIdx.x;
    if (idx >= NVZ*NFEAT) return;
    int o = idx / NFEAT, f = idx - o*NFEAT;
    g_wt[f*NVZ + o] = w[idx];
}

// per-node: pos4 (pos + |p|^2, plain asc rounding), ncac atoms, positions out
__global__ void setup_kernel(const float* __restrict__ aff,
                             const float* __restrict__ lit,
                             const void*  __restrict__ maskp,
                             float* __restrict__ out) {
    int i = blockIdx.x*256 + threadIdx.x;
    if (i >= NN) return;
    const float* A = aff + i*12;
    float r0=A[0], r1=A[1], r2=A[2],  tx=A[3];
    float r3=A[4], r4=A[5], r5=A[6],  ty=A[7];
    float r6=A[8], r7=A[9], r8=A[10], tz=A[11];
    float n2 = __fadd_rn(__fadd_rn(__fmul_rn(tx,tx), __fmul_rn(ty,ty)),
                         __fmul_rn(tz,tz));
    g_pos4[i] = make_float4(tx,ty,tz,n2);
    out[OFF_POS+i*3+0]=tx; out[OFF_POS+i*3+1]=ty; out[OFF_POS+i*3+2]=tz;

    int kind = g_mask_kind;
    bool mk;
    if (kind == 1)      mk = ((const unsigned char*)maskp)[i] != 0;
    else if (kind == 2) mk = ((const float*)maskp)[i] != 0.0f;
    else                mk = ((const int*)maskp)[i] != 0;
    const float* L = lit + (mk ? 0 : NUMPROT)*9;
    #pragma unroll
    for (int a = 0; a < 3; a++) {
        float lx=L[a*3+0], ly=L[a*3+1], lz=L[a*3+2];
        float px = fmaf(r0,lx, fmaf(r1,ly, r2*lz)) + tx;
        float py = fmaf(r3,lx, fmaf(r4,ly, r5*lz)) + ty;
        float pz = fmaf(r6,lx, fmaf(r7,ly, r8*lz)) + tz;
        g_ncac[i*3+a] = make_float4(px,py,pz,0.f);
    }
}

// ---------------------------------------------------------------------------
// kNN: warp handles TWO queries; 64 candidates per iteration (2 batches).
// Lane-distributed top-20 lists sorted lexicographically by (d2, index) —
// scan-order invariant, so batch order cannot change the result. Stale
// thresholds only enlarge the qualifier superset (threshold is monotone
// non-increasing); the live p<20 re-check inside the insert keeps exactness.
// d2 bits FROZEN: dot = fma(z,z', fma(y,y', rn(x*x')));
//                 d2  = rn(n2i + fma(-2,dot,n2j))
// ---------------------------------------------------------------------------
#define KTILE 2048
__global__ void __launch_bounds__(256) knn_kernel(float* __restrict__ out) {
    __shared__ float4 tile[KTILE];
    const unsigned FULL = 0xffffffffu;
    int warp = threadIdx.x >> 5;
    int lane = threadIdx.x & 31;
    int q0 = (blockIdx.x*8 + warp)*2;
    int q1 = q0 + 1;
    float4 P0 = g_pos4[q0];
    float4 P1 = g_pos4[q1];
    const float INF = __int_as_float(0x7f800000);
    float dist[2]; int idx[2];
    float thrd[2]; int thri[2];
    #pragma unroll
    for (int t = 0; t < 2; t++) {
        dist[t] = INF; idx[t] = 0x7FFFFFFF;
        thrd[t] = INF; thri[t] = 0x7FFFFFFF;
    }

    for (int t0 = 0; t0 < NN; t0 += KTILE) {
        __syncthreads();
        for (int i = threadIdx.x; i < KTILE; i += 256) tile[i] = g_pos4[t0+i];
        __syncthreads();
        for (int b = 0; b < KTILE; b += 64) {
            int ja = t0 + b + lane;
            int jb = ja + 32;
            float4 ca = tile[b + lane];
            float4 cb = tile[b + 32 + lane];
            // d2 for (q,batch) pairs, frozen bit pattern
            float dot0a = __fmaf_rn(P0.z, ca.z, __fmaf_rn(P0.y, ca.y, __fmul_rn(P0.x, ca.x)));
            float dot0b = __fmaf_rn(P0.z, cb.z, __fmaf_rn(P0.y, cb.y, __fmul_rn(P0.x, cb.x)));
            float dot1a = __fmaf_rn(P1.z, ca.z, __fmaf_rn(P1.y, ca.y, __fmul_rn(P1.x, ca.x)));
            float dot1b = __fmaf_rn(P1.z, cb.z, __fmaf_rn(P1.y, cb.y, __fmul_rn(P1.x, cb.x)));
            float d0a = __fadd_rn(P0.w, __fmaf_rn(-2.0f, dot0a, ca.w));
            float d0b = __fadd_rn(P0.w, __fmaf_rn(-2.0f, dot0b, cb.w));
            float d1a = __fadd_rn(P1.w, __fmaf_rn(-2.0f, dot1a, ca.w));
            float d1b = __fadd_rn(P1.w, __fmaf_rn(-2.0f, dot1b, cb.w));
            unsigned b0a = __ballot_sync(FULL, (ja != q0) &&
                (d0a < thrd[0] || (d0a == thrd[0] && ja < thri[0])));
            unsigned b0b = __ballot_sync(FULL, (jb != q0) &&
                (d0b < thrd[0] || (d0b == thrd[0] && jb < thri[0])));
            unsigned b1a = __ballot_sync(FULL, (ja != q1) &&
                (d1a < thrd[1] || (d1a == thrd[1] && ja < thri[1])));
            unsigned b1b = __ballot_sync(FULL, (jb != q1) &&
                (d1b < thrd[1] || (d1b == thrd[1] && jb < thri[1])));
            if (b0a | b0b | b1a | b1b) {
                #pragma unroll
                for (int sel = 0; sel < 4; sel++) {
                    int qq = sel >> 1;
                    unsigned bal = (sel==0)?b0a:(sel==1)?b0b:(sel==2)?b1a:b1b;
                    if (!bal) continue;
                    float dv = (sel==0)?d0a:(sel==1)?d0b:(sel==2)?d1a:d1b;
                    int jbase = t0 + b + ((sel & 1) ? 32 : 0);
                    do {
                        int src = __ffs(bal) - 1; bal &= bal - 1;
                        float cd = __shfl_sync(FULL, dv, src);
                        int   ci = jbase + src;
                        unsigned mlt = __ballot_sync(FULL,
                            (dist[qq] < cd) || (dist[qq] == cd && idx[qq] < ci)) & 0xFFFFFu;
                        int p = __popc(mlt);
                        if (p < 20) {
                            float nd = __shfl_up_sync(FULL, dist[qq], 1);
                            int   ni = __shfl_up_sync(FULL, idx[qq], 1);
                            if (lane >= p && lane < 20) {
                                dist[qq] = (lane == p) ? cd : nd;
                                idx[qq]  = (lane == p) ? ci : ni;
                            }
                        }
                    } while (bal);
                    thrd[qq] = __shfl_sync(FULL, dist[qq], 19);
                    thri[qq] = __shfl_sync(FULL, idx[qq], 19);
                }
            }
        }
    }
    if (lane < KZ) {
        #pragma unroll
        for (int qq = 0; qq < 2; qq++) {
            int q = q0 + qq;
            g_edge[q*KZ+lane] = idx[qq];
            out[OFF_EI  + q*KZ + lane] = (float)idx[qq];
            out[OFF_FEI + q*KZ + lane] = (float)idx[qq];
            out[OFF_FEI + NN*KZ + q*KZ + lane] = (float)q;
        }
    }
}

// ---------------------------------------------------------------------------
// Merged per-node geometry + encoding. 128 threads per node.
// ---------------------------------------------------------------------------
__global__ void __launch_bounds__(128) geom_enc_kernel(const float* __restrict__ aff,
                                                       float* __restrict__ out) {
    __shared__ float dl[NDIST];
    __shared__ float fl[PDIM/2];
    int n = blockIdx.x;
    int tid = threadIdx.x;
    if (tid < PDIM/2) fl[tid] = g_freq[tid];
    __syncthreads();

    if (tid < KZ) {
        int k = tid;
        const float* A = aff + n*12;
        float r0=A[0], r1=A[1], r2=A[2],  tx=A[3];
        float r3=A[4], r4=A[5], r5=A[6],  ty=A[7];
        float r6=A[8], r7=A[9], r8=A[10], tz=A[11];
        int j = g_edge[n*KZ+k];
        float4 nb = g_pos4[j];
        float vx = nb.x - tx, vy = nb.y - ty, vz = nb.z - tz;
        float ex = fmaf(r0,vx, fmaf(r3,vy, r6*vz));
        float ey = fmaf(r1,vx, fmaf(r4,vy, r7*vz));
        float ez = fmaf(r2,vx, fmaf(r5,vy, r8*vz));
        int eb = (n*KZ+k)*3;
        out[OFF_NP+eb+0]=ex; out[OFF_NP+eb+1]=ey; out[OFF_NP+eb+2]=ez;
        float nrm = sqrtf(fmaf(ex,ex, fmaf(ey,ey, ez*ez)));
        int db = (n*KZ+k)*PDIM;
        #pragma unroll
        for (int t = 0; t < PDIM/2; t++) {
            float sv, cv;
            sincos_poly(nrm * fl[t], sv, cv);
            out[OFF_ND+db+t]    = sv;
            out[OFF_ND+db+10+t] = cv;
        }
        float4 ca = g_ncac[n*3+1], np = g_ncac[n*3+0], cp = g_ncac[n*3+2];
        #pragma unroll
        for (int a = 0; a < 3; a++) {
            float4 p = g_ncac[j*3+a];
            float dx=p.x-ca.x, dy=p.y-ca.y, dz=p.z-ca.z;
            dl[k*3 + a] = sqrtf(fmaf(dx,dx, fmaf(dy,dy, dz*dz)));
        }
        {
            float4 p = g_ncac[j*3+2];
            float dx=p.x-np.x, dy=p.y-np.y, dz=p.z-np.z;
            dl[60 + k] = sqrtf(fmaf(dx,dx, fmaf(dy,dy, dz*dz)));
            float4 p2 = g_ncac[j*3+0];
            float ex2=p2.x-cp.x, ey2=p2.y-cp.y, ez2=p2.z-cp.z;
            dl[80 + k] = sqrtf(fmaf(ex2,ex2, fmaf(ey2,ey2, ez2*ez2)));
        }
    }
    __syncthreads();

    for (int f = tid; f < NDIST*(PDIM/2); f += 128) {
        int d = f / 10;
        int t = f - d*10;
        float sv, cv;
        sincos_poly(dl[d] * fl[t], sv, cv);
        g_enc[n*NFEAT + d*20 + t]      = sv;
        g_enc[n*NFEAT + d*20 + 10 + t] = cv;
    }
}

// ---------------------------------------------------------------------------
// GEMM (f32x2 packed FMA) + fused x-copy.
// ---------------------------------------------------------------------------
#define BK 16
__global__ void __launch_bounds__(256) gemm_kernel(const float* __restrict__ x,
                                                   float* __restrict__ out) {
    __shared__ float As[BK][68];
    __shared__ float Bs[BK][64];
    int tid = threadIdx.x;
    int tx = tid & 15, ty = tid >> 4;
    int m0 = blockIdx.x * 64;

    {
        const float4* xs = (const float4*)(x) + (size_t)m0*64;
        float4* od = (float4*)out;
        #pragma unroll
        for (int i = 0; i < 16; i++) {
            int e = tid + i*256;
            int r = e >> 6, c = e & 63;
            od[(size_t)(m0+r)*80 + c] = xs[e];
        }
    }

    u64 acc[4][2];
    #pragma unroll
    for (int a = 0; a < 4; a++) { acc[a][0] = pack2(0.f,0.f); acc[a][1] = pack2(0.f,0.f); }

    const float* Ag = g_enc + (size_t)m0 * NFEAT;
    for (int kt = 0; kt < NFEAT; kt += BK) {
        #pragma unroll
        for (int i = 0; i < 4; i++) {
            int e = tid + i*256;
            int m = e >> 4, kk = e & 15;
            As[kk][m] = Ag[m*NFEAT + kt + kk];
        }
        #pragma unroll
        for (int i = 0; i < 4; i++) {
            int e = tid + i*256;
            int kk = e >> 6, nn = e & 63;
            Bs[kk][nn] = g_wt[(kt+kk)*NVZ + nn];
        }
        __syncthreads();
        #pragma unroll
        for (int kk = 0; kk < BK; kk++) {
            float4 a = *(const float4*)&As[kk][ty*4];
            const u64* bp = (const u64*)&Bs[kk][tx*4];
            u64 b01 = bp[0], b23 = bp[1];
            float av[4] = {a.x,a.y,a.z,a.w};
            #pragma unroll
            for (int i = 0; i < 4; i++) {
                u64 ai = pack2(av[i], av[i]);
                acc[i][0] = ffma2(ai, b01, acc[i][0]);
                acc[i][1] = ffma2(ai, b23, acc[i][1]);
            }
        }
        __syncthreads();
    }
    #pragma unroll
    for (int i = 0; i < 4; i++) {
        int m = m0 + ty*4 + i;
        float c0,c1,c2,c3;
        unpack2(acc[i][0], c0, c1);
        unpack2(acc[i][1], c2, c3);
        float* od = out + (size_t)m*(FZ+NVZ) + FZ + tx*4;
        od[0]=c0; od[1]=c1; od[2]=c2; od[3]=c3;
    }
}

extern "C" void kernel_launch(void* const* d_in, const int* in_sizes, int n_in,
                              void* d_out, int out_size) {
    const float* x    = (const float*)d_in[0];
    const float* aff  = (const float*)d_in[1];
    const float* nw   = (const float*)d_in[2];
    const float* lit  = (const float*)d_in[3];
    const void*  mask = d_in[4];
    float* out = (float*)d_out;

    detect_kernel<<<1, 256>>>((const unsigned int*)mask);
    wt_kernel<<<(NVZ*NFEAT + 255)/256, 256>>>(nw);
    setup_kernel<<<(NN+255)/256, 256>>>(aff, lit, mask, out);
    knn_kernel<<<NN/16, 256>>>(out);
    geom_enc_kernel<<<NN, 128>>>(aff, out);
    gemm_kernel<<<NN/64, 256>>>(x, out);
}

// round 14
// speedup vs baseline: 1.5109x; 1.3259x over previous
#include <cuda_runtime.h>
#include <math.h>

#define NN      8192
#define KZ      20
#define PDIM    20
#define NVZ     64
#define NUMPROT 20
#define FZ      256
#define NFEAT   2000
#define NDIST   100

// output layout: tuple members concatenated, float32
#define OFF_POS (NN*(FZ+NVZ))
#define OFF_NP  (OFF_POS + NN*3)
#define OFF_ND  (OFF_NP  + NN*KZ*3)
#define OFF_EI  (OFF_ND  + NN*KZ*PDIM)
#define OFF_FEI (OFF_EI  + NN*KZ)

typedef unsigned long long u64;

// device scratch (allocation-free rule -> static globals)
__device__ float4 g_pos4[NN];
__device__ float4 g_ncac[NN*3];
__device__ int    g_edge[NN*KZ];
__device__ float  g_dist[NN*NDIST];
__device__ float  g_wt[NFEAT*NVZ];
__device__ float  g_freq[PDIM/2];
__device__ int    g_mask_kind;

__device__ __forceinline__ u64 ffma2(u64 a, u64 b, u64 c) {
    u64 d;
    asm("fma.rn.f32x2 %0, %1, %2, %3;" : "=l"(d) : "l"(a), "l"(b), "l"(c));
    return d;
}
__device__ __forceinline__ u64 pack2(float x, float y) {
    u64 r;
    asm("mov.b64 %0, {%1, %2};" : "=l"(r) : "f"(x), "f"(y));
    return r;
}
__device__ __forceinline__ void unpack2(u64 v, float& x, float& y) {
    asm("mov.b64 {%0, %1}, %2;" : "=f"(x), "=f"(y) : "l"(v));
}

// ---------------------------------------------------------------------------
// FMA-pipe sincos (abs err < 4e-6 for |x| < 25)
// ---------------------------------------------------------------------------
__device__ __forceinline__ void sincos_poly(float x, float& so, float& co) {
    float q = rintf(x * 0.6366197723675814f);
    int iq = (int)q;
    float r = fmaf(-q, 1.57079637050628662109375f, x);
    r = fmaf(-q, -4.37113900018624283e-8f, r);
    float r2 = r * r;
    float ps = fmaf(-1.9841270114e-4f, r2, 8.3333337680e-3f);
    ps = fmaf(ps, r2, -1.6666667163e-1f);
    float sinr = fmaf(ps * r2, r, r);
    float pc = fmaf(-1.3888889225e-3f, r2, 4.1666667908e-2f);
    pc = fmaf(pc, r2, -0.5f);
    float cosr = fmaf(pc, r2, 1.0f);
    int qq = iq & 3;
    float s_ = (qq & 1) ? cosr : sinr;
    float c_ = (qq & 1) ? sinr : cosr;
    if (qq == 1 || qq == 2) c_ = -c_;
    if (qq >= 2) s_ = -s_;
    so = s_; co = c_;
}

// ---------------------------------------------------------------------------
// Classify prot_mask storage: 0=int32(0/1 words), 1=uint8, 2=float32.
// ---------------------------------------------------------------------------
__global__ void detect_kernel(const unsigned int* __restrict__ m) {
    __shared__ int red[256];
    int t = threadIdx.x;
    int code = 0;
    for (int i = t; i < 2048; i += 256) {
        unsigned w = m[i];
        if (w == 0x3F800000u) code = 2;
        else if (w != 0u && w != 1u) code = max(code, 1);
    }
    red[t] = code; __syncthreads();
    for (int s = 128; s > 0; s >>= 1) {
        if (t < s) red[t] = max(red[t], red[t+s]);
        __syncthreads();
    }
    if (t == 0) g_mask_kind = red[0];
    if (t < PDIM/2) g_freq[t] = (float)exp(-0.39120230054281463 * (double)t);
}

// ne_weight (64,2000) -> g_wt (2000,64)
__global__ void wt_kernel(const float* __restrict__ w) {
    int idx = blockIdx.x*256 + threadIdx.x;
    if (idx >= NVZ*NFEAT) return;
    int o = idx / NFEAT, f = idx - o*NFEAT;
    g_wt[f*NVZ + o] = w[idx];
}

// per-node: pos4 (pos + |p|^2, plain asc rounding), ncac atoms, positions out
__global__ void setup_kernel(const float* __restrict__ aff,
                             const float* __restrict__ lit,
                             const void*  __restrict__ maskp,
                             float* __restrict__ out) {
    int i = blockIdx.x*256 + threadIdx.x;
    if (i >= NN) return;
    const float* A = aff + i*12;
    float r0=A[0], r1=A[1], r2=A[2],  tx=A[3];
    float r3=A[4], r4=A[5], r5=A[6],  ty=A[7];
    float r6=A[8], r7=A[9], r8=A[10], tz=A[11];
    float n2 = __fadd_rn(__fadd_rn(__fmul_rn(tx,tx), __fmul_rn(ty,ty)),
                         __fmul_rn(tz,tz));
    g_pos4[i] = make_float4(tx,ty,tz,n2);
    out[OFF_POS+i*3+0]=tx; out[OFF_POS+i*3+1]=ty; out[OFF_POS+i*3+2]=tz;

    int kind = g_mask_kind;
    bool mk;
    if (kind == 1)      mk = ((const unsigned char*)maskp)[i] != 0;
    else if (kind == 2) mk = ((const float*)maskp)[i] != 0.0f;
    else                mk = ((const int*)maskp)[i] != 0;
    const float* L = lit + (mk ? 0 : NUMPROT)*9;
    #pragma unroll
    for (int a = 0; a < 3; a++) {
        float lx=L[a*3+0], ly=L[a*3+1], lz=L[a*3+2];
        float px = fmaf(r0,lx, fmaf(r1,ly, r2*lz)) + tx;
        float py = fmaf(r3,lx, fmaf(r4,ly, r5*lz)) + ty;
        float pz = fmaf(r6,lx, fmaf(r7,ly, r8*lz)) + tz;
        g_ncac[i*3+a] = make_float4(px,py,pz,0.f);
    }
}

// ---------------------------------------------------------------------------
// kNN: 1 query/warp, slim qualifier: single d2<=thr compare. Ties with
// larger index and the self-candidate are admitted to the rare insert path
// and rejected there (live lexicographic position check), so the final list
// is identical to the passing strict-<, ascending-j semantics.
// d2 bits FROZEN: dot = fma(z,z', fma(y,y', rn(x*x')));
//                 d2  = rn(n2i + fma(-2,dot,n2j))
// ---------------------------------------------------------------------------
#define KTILE 2048
__global__ void __launch_bounds__(256) knn_kernel(float* __restrict__ out) {
    __shared__ float4 tile[KTILE];
    const unsigned FULL = 0xffffffffu;
    int warp = threadIdx.x >> 5;
    int lane = threadIdx.x & 31;
    int q = blockIdx.x*8 + warp;
    float4 P = g_pos4[q];
    const float INF = __int_as_float(0x7f800000);
    float dist = INF;
    int   idx  = 0x7FFFFFFF;
    float thrd = INF;

    for (int t0 = 0; t0 < NN; t0 += KTILE) {
        __syncthreads();
        for (int i = threadIdx.x; i < KTILE; i += 256) tile[i] = g_pos4[t0+i];
        __syncthreads();
        #pragma unroll 4
        for (int b = 0; b < KTILE; b += 32) {
            float4 c = tile[b + lane];
            float dot = __fmaf_rn(P.z, c.z,
                        __fmaf_rn(P.y, c.y, __fmul_rn(P.x, c.x)));
            float d2  = __fadd_rn(P.w, __fmaf_rn(-2.0f, dot, c.w));
            unsigned bal = __ballot_sync(FULL, d2 <= thrd);
            if (bal) {
                do {
                    int src = __ffs(bal) - 1; bal &= bal - 1;
                    float cd = __shfl_sync(FULL, d2, src);
                    int   ci = t0 + b + src;
                    if (ci != q) {   // warp-uniform
                        unsigned mlt = __ballot_sync(FULL,
                            (dist < cd) || (dist == cd && idx < ci)) & 0xFFFFFu;
                        int p = __popc(mlt);
                        if (p < 20) {
                            float nd = __shfl_up_sync(FULL, dist, 1);
                            int   ni = __shfl_up_sync(FULL, idx, 1);
                            if (lane >= p && lane < 20) {
                                dist = (lane == p) ? cd : nd;
                                idx  = (lane == p) ? ci : ni;
                            }
                        }
                    }
                } while (bal);
                thrd = __shfl_sync(FULL, dist, 19);
            }
        }
    }
    if (lane < KZ) {
        g_edge[q*KZ+lane] = idx;
        out[OFF_EI  + q*KZ + lane] = (float)idx;
        out[OFF_FEI + q*KZ + lane] = (float)idx;
        out[OFF_FEI + NN*KZ + q*KZ + lane] = (float)q;
    }
}

// ---------------------------------------------------------------------------
// Per-edge geometry: neighbour_positions, neighbour distance encoding (poly),
// and the 100 backbone distances per node into g_dist (for the fused GEMM).
// ---------------------------------------------------------------------------
__global__ void geom_kernel(const float* __restrict__ aff,
                            float* __restrict__ out) {
    int n = blockIdx.x;
    int k = threadIdx.x;
    if (k >= KZ) return;
    const float* A = aff + n*12;
    float r0=A[0], r1=A[1], r2=A[2],  tx=A[3];
    float r3=A[4], r4=A[5], r5=A[6],  ty=A[7];
    float r6=A[8], r7=A[9], r8=A[10], tz=A[11];
    int j = g_edge[n*KZ+k];
    float4 nb = g_pos4[j];
    float vx = nb.x - tx, vy = nb.y - ty, vz = nb.z - tz;
    float ex = fmaf(r0,vx, fmaf(r3,vy, r6*vz));
    float ey = fmaf(r1,vx, fmaf(r4,vy, r7*vz));
    float ez = fmaf(r2,vx, fmaf(r5,vy, r8*vz));
    int eb = (n*KZ+k)*3;
    out[OFF_NP+eb+0]=ex; out[OFF_NP+eb+1]=ey; out[OFF_NP+eb+2]=ez;
    float nrm = sqrtf(fmaf(ex,ex, fmaf(ey,ey, ez*ez)));
    int db = (n*KZ+k)*PDIM;
    #pragma unroll
    for (int t = 0; t < PDIM/2; t++) {
        float sv, cv;
        sincos_poly(nrm * g_freq[t], sv, cv);
        out[OFF_ND+db+t]    = sv;
        out[OFF_ND+db+10+t] = cv;
    }
    float4 ca = g_ncac[n*3+1], np = g_ncac[n*3+0], cp = g_ncac[n*3+2];
    #pragma unroll
    for (int a = 0; a < 3; a++) {
        float4 p = g_ncac[j*3+a];
        float dx=p.x-ca.x, dy=p.y-ca.y, dz=p.z-ca.z;
        g_dist[n*NDIST + k*3 + a] = sqrtf(fmaf(dx,dx, fmaf(dy,dy, dz*dz)));
    }
    {
        float4 p = g_ncac[j*3+2];
        float dx=p.x-np.x, dy=p.y-np.y, dz=p.z-np.z;
        g_dist[n*NDIST + 60 + k] = sqrtf(fmaf(dx,dx, fmaf(dy,dy, dz*dz)));
        float4 p2 = g_ncac[j*3+0];
        float ex2=p2.x-cp.x, ey2=p2.y-cp.y, ez2=p2.z-cp.z;
        g_dist[n*NDIST + 80 + k] = sqrtf(fmaf(ex2,ex2, fmaf(ey2,ey2, ez2*ez2)));
    }
}

// ---------------------------------------------------------------------------
// Fused enc+GEMM (+x copy). C(8192x64) = enc(8192x2000) @ g_wt(2000x64).
// BK=20 = one distance group; the A-tile is GENERATED in smem by sincos_poly
// from staged distances (no global enc array at all). B double-buffered via
// registers. All wide-accessed shared arrays are 16B-aligned (LDS.128 trap
// otherwise — round-13 bug). k ascending 0..1999 with identical per-element
// fma chain and identical sincos bits -> embedding bitwise identical.
// ---------------------------------------------------------------------------
#define GBK 20
__global__ void __launch_bounds__(256) gemm_kernel(const float* __restrict__ x,
                                                   float* __restrict__ out) {
    __shared__ __align__(16) float dl[NDIST][65];      // [d][m], padded
    __shared__ __align__(16) float fl[PDIM/2];
    __shared__ __align__(16) float As[GBK][68];        // [r][m], padded (68*4=272, 16B multiple)
    __shared__ __align__(16) float Bs[2][GBK][64];     // [r][n], double-buffered
    int tid = threadIdx.x;
    int tx = tid & 15, ty = tid >> 4;
    int m0 = blockIdx.x * 64;

    // fused copyx: rows m0..m0+63, 256 floats each
    {
        const float4* xs = (const float4*)(x) + (size_t)m0*64;
        float4* od = (float4*)out;
        #pragma unroll
        for (int i = 0; i < 16; i++) {
            int e = tid + i*256;
            int r = e >> 6, c = e & 63;
            od[(size_t)(m0+r)*80 + c] = xs[e];
        }
    }

    if (tid < PDIM/2) fl[tid] = g_freq[tid];
    // stage distances: dl[d][m] = g_dist[(m0+m)*100 + d], coalesced reads
    for (int i = tid; i < 64*NDIST; i += 256) {
        int m = i / NDIST, d = i - m*NDIST;
        dl[d][m] = g_dist[(size_t)(m0+m)*NDIST + d];
    }
    // preload B tile 0
    #pragma unroll
    for (int i = 0; i < 5; i++) {
        int e = tid + i*256;
        Bs[0][e>>6][e&63] = g_wt[(e>>6)*NVZ + (e&63)];
    }
    __syncthreads();

    u64 acc[4][2];
    #pragma unroll
    for (int a = 0; a < 4; a++) { acc[a][0] = pack2(0.f,0.f); acc[a][1] = pack2(0.f,0.f); }

    for (int d = 0; d < NDIST; d++) {
        int cur = d & 1;
        float pb[5];
        if (d < NDIST-1) {
            #pragma unroll
            for (int i = 0; i < 5; i++) {
                int e = tid + i*256;
                pb[i] = g_wt[((d+1)*GBK + (e>>6))*NVZ + (e&63)];
            }
        }
        // generate A tile: 640 sincos pairs
        for (int f = tid; f < 640; f += 256) {
            int m = f & 63, t = f >> 6;
            float sv, cv;
            sincos_poly(dl[d][m] * fl[t], sv, cv);
            As[t][m]    = sv;
            As[t+10][m] = cv;
        }
        __syncthreads();
        #pragma unroll
        for (int kk = 0; kk < GBK; kk++) {
            float4 a = *(const float4*)&As[kk][ty*4];
            const u64* bp = (const u64*)&Bs[cur][kk][tx*4];
            u64 b01 = bp[0], b23 = bp[1];
            float av[4] = {a.x,a.y,a.z,a.w};
            #pragma unroll
            for (int i = 0; i < 4; i++) {
                u64 ai = pack2(av[i], av[i]);
                acc[i][0] = ffma2(ai, b01, acc[i][0]);
                acc[i][1] = ffma2(ai, b23, acc[i][1]);
            }
        }
        __syncthreads();
        if (d < NDIST-1) {
            #pragma unroll
            for (int i = 0; i < 5; i++) {
                int e = tid + i*256;
                Bs[cur^1][e>>6][e&63] = pb[i];
            }
        }
    }
    #pragma unroll
    for (int i = 0; i < 4; i++) {
        int m = m0 + ty*4 + i;
        float c0,c1,c2,c3;
        unpack2(acc[i][0], c0, c1);
        unpack2(acc[i][1], c2, c3);
        float* od = out + (size_t)m*(FZ+NVZ) + FZ + tx*4;
        od[0]=c0; od[1]=c1; od[2]=c2; od[3]=c3;
    }
}

extern "C" void kernel_launch(void* const* d_in, const int* in_sizes, int n_in,
                              void* d_out, int out_size) {
    const float* x    = (const float*)d_in[0];
    const float* aff  = (const float*)d_in[1];
    const float* nw   = (const float*)d_in[2];
    const float* lit  = (const float*)d_in[3];
    const void*  mask = d_in[4];
    float* out = (float*)d_out;

    detect_kernel<<<1, 256>>>((const unsigned int*)mask);
    wt_kernel<<<(NVZ*NFEAT + 255)/256, 256>>>(nw);
    setup_kernel<<<(NN+255)/256, 256>>>(aff, lit, mask, out);
    knn_kernel<<<NN/8, 256>>>(out);
    geom_kernel<<<NN, 32>>>(aff, out);
    gemm_kernel<<<NN/64, 256>>>(x, out);
}

// round 15
// speedup vs baseline: 1.5462x; 1.0234x over previous
#include <cuda_runtime.h>
#include <math.h>

#define NN      8192
#define KZ      20
#define PDIM    20
#define NVZ     64
#define NUMPROT 20
#define FZ      256
#define NFEAT   2000
#define NDIST   100
#define NBUCK   4096

// output layout: tuple members concatenated, float32
#define OFF_POS (NN*(FZ+NVZ))
#define OFF_NP  (OFF_POS + NN*3)
#define OFF_ND  (OFF_NP  + NN*KZ*3)
#define OFF_EI  (OFF_ND  + NN*KZ*PDIM)
#define OFF_FEI (OFF_EI  + NN*KZ)

typedef unsigned long long u64;

// device scratch (allocation-free rule -> static globals)
__device__ float4 g_pos4[NN];
__device__ float4 g_spos4[NN];   // z-bucket-sorted positions (+n2)
__device__ int    g_sidx[NN];    // sorted pos -> original index
__device__ int    g_pq[NN];      // original index -> sorted pos
__device__ int    g_hist[NBUCK];
__device__ int    g_off[NBUCK];
__device__ float4 g_ncac[NN*3];
__device__ int    g_edge[NN*KZ];
__device__ float  g_dist[NN*NDIST];
__device__ float  g_wt[NFEAT*NVZ];
__device__ float  g_freq[PDIM/2];
__device__ int    g_mask_kind;

__device__ __forceinline__ u64 ffma2(u64 a, u64 b, u64 c) {
    u64 d;
    asm("fma.rn.f32x2 %0, %1, %2, %3;" : "=l"(d) : "l"(a), "l"(b), "l"(c));
    return d;
}
__device__ __forceinline__ u64 pack2(float x, float y) {
    u64 r;
    asm("mov.b64 %0, {%1, %2};" : "=l"(r) : "f"(x), "f"(y));
    return r;
}
__device__ __forceinline__ void unpack2(u64 v, float& x, float& y) {
    asm("mov.b64 {%0, %1}, %2;" : "=f"(x), "=f"(y) : "l"(v));
}

__device__ __forceinline__ int zbucket(float z) {
    int b = (int)((z + 16.0f) * 128.0f);   // 4096 buckets over [-16,16]
    return min(max(b, 0), NBUCK-1);
}

// ---------------------------------------------------------------------------
// FMA-pipe sincos (abs err < 4e-6 for |x| < 25)
// ---------------------------------------------------------------------------
__device__ __forceinline__ void sincos_poly(float x, float& so, float& co) {
    float q = rintf(x * 0.6366197723675814f);
    int iq = (int)q;
    float r = fmaf(-q, 1.57079637050628662109375f, x);
    r = fmaf(-q, -4.37113900018624283e-8f, r);
    float r2 = r * r;
    float ps = fmaf(-1.9841270114e-4f, r2, 8.3333337680e-3f);
    ps = fmaf(ps, r2, -1.6666667163e-1f);
    float sinr = fmaf(ps * r2, r, r);
    float pc = fmaf(-1.3888889225e-3f, r2, 4.1666667908e-2f);
    pc = fmaf(pc, r2, -0.5f);
    float cosr = fmaf(pc, r2, 1.0f);
    int qq = iq & 3;
    float s_ = (qq & 1) ? cosr : sinr;
    float c_ = (qq & 1) ? sinr : cosr;
    if (qq == 1 || qq == 2) c_ = -c_;
    if (qq >= 2) s_ = -s_;
    so = s_; co = c_;
}

// ---------------------------------------------------------------------------
// Classify prot_mask + freqs + zero the z-histogram.
// ---------------------------------------------------------------------------
__global__ void detect_kernel(const unsigned int* __restrict__ m) {
    __shared__ int red[256];
    int t = threadIdx.x;
    int code = 0;
    for (int i = t; i < 2048; i += 256) {
        unsigned w = m[i];
        if (w == 0x3F800000u) code = 2;
        else if (w != 0u && w != 1u) code = max(code, 1);
    }
    red[t] = code; __syncthreads();
    for (int s = 128; s > 0; s >>= 1) {
        if (t < s) red[t] = max(red[t], red[t+s]);
        __syncthreads();
    }
    if (t == 0) g_mask_kind = red[0];
    if (t < PDIM/2) g_freq[t] = (float)exp(-0.39120230054281463 * (double)t);
    for (int i = t; i < NBUCK; i += 256) g_hist[i] = 0;
}

// ne_weight (64,2000) -> g_wt (2000,64)
__global__ void wt_kernel(const float* __restrict__ w) {
    int idx = blockIdx.x*256 + threadIdx.x;
    if (idx >= NVZ*NFEAT) return;
    int o = idx / NFEAT, f = idx - o*NFEAT;
    g_wt[f*NVZ + o] = w[idx];
}

// per-node: pos4 (pos + |p|^2), ncac atoms, positions out, z-histogram
__global__ void setup_kernel(const float* __restrict__ aff,
                             const float* __restrict__ lit,
                             const void*  __restrict__ maskp,
                             float* __restrict__ out) {
    int i = blockIdx.x*256 + threadIdx.x;
    if (i >= NN) return;
    const float* A = aff + i*12;
    float r0=A[0], r1=A[1], r2=A[2],  tx=A[3];
    float r3=A[4], r4=A[5], r5=A[6],  ty=A[7];
    float r6=A[8], r7=A[9], r8=A[10], tz=A[11];
    float n2 = __fadd_rn(__fadd_rn(__fmul_rn(tx,tx), __fmul_rn(ty,ty)),
                         __fmul_rn(tz,tz));
    g_pos4[i] = make_float4(tx,ty,tz,n2);
    out[OFF_POS+i*3+0]=tx; out[OFF_POS+i*3+1]=ty; out[OFF_POS+i*3+2]=tz;
    atomicAdd(&g_hist[zbucket(tz)], 1);

    int kind = g_mask_kind;
    bool mk;
    if (kind == 1)      mk = ((const unsigned char*)maskp)[i] != 0;
    else if (kind == 2) mk = ((const float*)maskp)[i] != 0.0f;
    else                mk = ((const int*)maskp)[i] != 0;
    const float* L = lit + (mk ? 0 : NUMPROT)*9;
    #pragma unroll
    for (int a = 0; a < 3; a++) {
        float lx=L[a*3+0], ly=L[a*3+1], lz=L[a*3+2];
        float px = fmaf(r0,lx, fmaf(r1,ly, r2*lz)) + tx;
        float py = fmaf(r3,lx, fmaf(r4,ly, r5*lz)) + ty;
        float pz = fmaf(r6,lx, fmaf(r7,ly, r8*lz)) + tz;
        g_ncac[i*3+a] = make_float4(px,py,pz,0.f);
    }
}

// exclusive prefix over 4096 bucket counts (1 block, 1024 threads)
__global__ void prefix_kernel() {
    __shared__ int s[1024];
    int t = threadIdx.x;
    int a0 = g_hist[t*4+0], a1 = g_hist[t*4+1];
    int a2 = g_hist[t*4+2], a3 = g_hist[t*4+3];
    int sum = a0+a1+a2+a3;
    s[t] = sum;
    __syncthreads();
    for (int off = 1; off < 1024; off <<= 1) {
        int v = (t >= off) ? s[t-off] : 0;
        __syncthreads();
        s[t] += v;
        __syncthreads();
    }
    int excl = s[t] - sum;
    g_off[t*4+0] = excl;
    g_off[t*4+1] = excl + a0;
    g_off[t*4+2] = excl + a0 + a1;
    g_off[t*4+3] = excl + a0 + a1 + a2;
}

// scatter into z-sorted order (within-bucket order arbitrary -> harmless,
// final top-20 is lexicographic-unique and scan-order invariant)
__global__ void scatter_kernel() {
    int i = blockIdx.x*256 + threadIdx.x;
    if (i >= NN) return;
    float4 p = g_pos4[i];
    int b = zbucket(p.z);
    int pos = atomicAdd(&g_off[b], 1);
    g_spos4[pos] = p;
    g_sidx[pos]  = i;
    g_pq[i]      = pos;
}

// ---------------------------------------------------------------------------
// kNN with exact z-window pruning. 1 query/warp. Walks 32-candidate chunks
// outward from the query's sorted position; a side stops when even the
// closest possible remaining z-distance exceeds the current threshold
// (W covers within-bucket disorder; margin covers d2 rounding eps, since
// (dz)^2 <= true d2 <= computed d2 + eps).
// d2 bits FROZEN: dot = fma(z,z', fma(y,y', rn(x*x')));
//                 d2  = rn(n2i + fma(-2,dot,n2j))
// ---------------------------------------------------------------------------
__global__ void __launch_bounds__(256) knn_kernel(float* __restrict__ out) {
    const unsigned FULL = 0xffffffffu;
    int warp = threadIdx.x >> 5;
    int lane = threadIdx.x & 31;
    int q = blockIdx.x*8 + warp;
    float4 P = g_pos4[q];
    float zq = P.z;
    int pq = g_pq[q];
    const float INF = __int_as_float(0x7f800000);
    const float W = 0.0085f;     // > bucket width 32/4096
    float dist = INF;
    int   idx  = 0x7FFFFFFF;
    float thrd = INF;

    int cR = pq >> 5;
    int cL = cR - 1;
    bool doneR = false;
    bool doneL = (cL < 0);

    while (!doneR || !doneL) {
        if (!doneR) {
            int base = cR << 5;
            float4 c = g_spos4[base + lane];
            float dot = __fmaf_rn(P.z, c.z,
                        __fmaf_rn(P.y, c.y, __fmul_rn(P.x, c.x)));
            float d2  = __fadd_rn(P.w, __fmaf_rn(-2.0f, dot, c.w));
            unsigned bal = __ballot_sync(FULL, d2 <= thrd);
            if (bal) {
                do {
                    int src = __ffs(bal) - 1; bal &= bal - 1;
                    float cd = __shfl_sync(FULL, d2, src);
                    int   ci = g_sidx[base + src];
                    if (ci != q) {
                        unsigned mlt = __ballot_sync(FULL,
                            (dist < cd) || (dist == cd && idx < ci)) & 0xFFFFFu;
                        int p = __popc(mlt);
                        if (p < 20) {
                            float nd = __shfl_up_sync(FULL, dist, 1);
                            int   ni = __shfl_up_sync(FULL, idx, 1);
                            if (lane >= p && lane < 20) {
                                dist = (lane == p) ? cd : nd;
                                idx  = (lane == p) ? ci : ni;
                            }
                        }
                    }
                } while (bal);
                thrd = __shfl_sync(FULL, dist, 19);
            }
            float zhi = __shfl_sync(FULL, c.z, 31);
            float dz = zhi - zq - W;
            if (dz > 0.f && dz*dz > __fmaf_rn(thrd, 1.0001f, 1e-5f)) doneR = true;
            cR++;
            if (cR >= NN/32) doneR = true;
        }
        if (!doneL) {
            int base = cL << 5;
            float4 c = g_spos4[base + lane];
            float dot = __fmaf_rn(P.z, c.z,
                        __fmaf_rn(P.y, c.y, __fmul_rn(P.x, c.x)));
            float d2  = __fadd_rn(P.w, __fmaf_rn(-2.0f, dot, c.w));
            unsigned bal = __ballot_sync(FULL, d2 <= thrd);
            if (bal) {
                do {
                    int src = __ffs(bal) - 1; bal &= bal - 1;
                    float cd = __shfl_sync(FULL, d2, src);
                    int   ci = g_sidx[base + src];
                    if (ci != q) {
                        unsigned mlt = __ballot_sync(FULL,
                            (dist < cd) || (dist == cd && idx < ci)) & 0xFFFFFu;
                        int p = __popc(mlt);
                        if (p < 20) {
                            float nd = __shfl_up_sync(FULL, dist, 1);
                            int   ni = __shfl_up_sync(FULL, idx, 1);
                            if (lane >= p && lane < 20) {
                                dist = (lane == p) ? cd : nd;
                                idx  = (lane == p) ? ci : ni;
                            }
                        }
                    }
                } while (bal);
                thrd = __shfl_sync(FULL, dist, 19);
            }
            float zlo = __shfl_sync(FULL, c.z, 0);
            float dz = zq - zlo - W;
            if (dz > 0.f && dz*dz > __fmaf_rn(thrd, 1.0001f, 1e-5f)) doneL = true;
            cL--;
            if (cL < 0) doneL = true;
        }
    }
    if (lane < KZ) {
        g_edge[q*KZ+lane] = idx;
        out[OFF_EI  + q*KZ + lane] = (float)idx;
        out[OFF_FEI + q*KZ + lane] = (float)idx;
        out[OFF_FEI + NN*KZ + q*KZ + lane] = (float)q;
    }
}

// ---------------------------------------------------------------------------
// Per-edge geometry: neighbour_positions, neighbour distance encoding (poly),
// and the 100 backbone distances per node into g_dist (for the fused GEMM).
// ---------------------------------------------------------------------------
__global__ void geom_kernel(const float* __restrict__ aff,
                            float* __restrict__ out) {
    int n = blockIdx.x;
    int k = threadIdx.x;
    if (k >= KZ) return;
    const float* A = aff + n*12;
    float r0=A[0], r1=A[1], r2=A[2],  tx=A[3];
    float r3=A[4], r4=A[5], r5=A[6],  ty=A[7];
    float r6=A[8], r7=A[9], r8=A[10], tz=A[11];
    int j = g_edge[n*KZ+k];
    float4 nb = g_pos4[j];
    float vx = nb.x - tx, vy = nb.y - ty, vz = nb.z - tz;
    float ex = fmaf(r0,vx, fmaf(r3,vy, r6*vz));
    float ey = fmaf(r1,vx, fmaf(r4,vy, r7*vz));
    float ez = fmaf(r2,vx, fmaf(r5,vy, r8*vz));
    int eb = (n*KZ+k)*3;
    out[OFF_NP+eb+0]=ex; out[OFF_NP+eb+1]=ey; out[OFF_NP+eb+2]=ez;
    float nrm = sqrtf(fmaf(ex,ex, fmaf(ey,ey, ez*ez)));
    int db = (n*KZ+k)*PDIM;
    #pragma unroll
    for (int t = 0; t < PDIM/2; t++) {
        float sv, cv;
        sincos_poly(nrm * g_freq[t], sv, cv);
        out[OFF_ND+db+t]    = sv;
        out[OFF_ND+db+10+t] = cv;
    }
    float4 ca = g_ncac[n*3+1], np = g_ncac[n*3+0], cp = g_ncac[n*3+2];
    #pragma unroll
    for (int a = 0; a < 3; a++) {
        float4 p = g_ncac[j*3+a];
        float dx=p.x-ca.x, dy=p.y-ca.y, dz=p.z-ca.z;
        g_dist[n*NDIST + k*3 + a] = sqrtf(fmaf(dx,dx, fmaf(dy,dy, dz*dz)));
    }
    {
        float4 p = g_ncac[j*3+2];
        float dx=p.x-np.x, dy=p.y-np.y, dz=p.z-np.z;
        g_dist[n*NDIST + 60 + k] = sqrtf(fmaf(dx,dx, fmaf(dy,dy, dz*dz)));
        float4 p2 = g_ncac[j*3+0];
        float ex2=p2.x-cp.x, ey2=p2.y-cp.y, ez2=p2.z-cp.z;
        g_dist[n*NDIST + 80 + k] = sqrtf(fmaf(ex2,ex2, fmaf(ey2,ey2, ez2*ez2)));
    }
}

// ---------------------------------------------------------------------------
// Fused enc+GEMM (+x copy). C(8192x64) = enc(8192x2000) @ g_wt(2000x64).
// A-tile generated in smem by sincos_poly from staged distances. 16B-aligned
// shared arrays (LDS.128). Bitwise identical embedding (same fma chain).
// ---------------------------------------------------------------------------
#define GBK 20
__global__ void __launch_bounds__(256) gemm_kernel(const float* __restrict__ x,
                                                   float* __restrict__ out) {
    __shared__ __align__(16) float dl[NDIST][65];
    __shared__ __align__(16) float fl[PDIM/2];
    __shared__ __align__(16) float As[GBK][68];
    __shared__ __align__(16) float Bs[2][GBK][64];
    int tid = threadIdx.x;
    int tx = tid & 15, ty = tid >> 4;
    int m0 = blockIdx.x * 64;

    {
        const float4* xs = (const float4*)(x) + (size_t)m0*64;
        float4* od = (float4*)out;
        #pragma unroll
        for (int i = 0; i < 16; i++) {
            int e = tid + i*256;
            int r = e >> 6, c = e & 63;
            od[(size_t)(m0+r)*80 + c] = xs[e];
        }
    }

    if (tid < PDIM/2) fl[tid] = g_freq[tid];
    for (int i = tid; i < 64*NDIST; i += 256) {
        int m = i / NDIST, d = i - m*NDIST;
        dl[d][m] = g_dist[(size_t)(m0+m)*NDIST + d];
    }
    #pragma unroll
    for (int i = 0; i < 5; i++) {
        int e = tid + i*256;
        Bs[0][e>>6][e&63] = g_wt[(e>>6)*NVZ + (e&63)];
    }
    __syncthreads();

    u64 acc[4][2];
    #pragma unroll
    for (int a = 0; a < 4; a++) { acc[a][0] = pack2(0.f,0.f); acc[a][1] = pack2(0.f,0.f); }

    for (int d = 0; d < NDIST; d++) {
        int cur = d & 1;
        float pb[5];
        if (d < NDIST-1) {
            #pragma unroll
            for (int i = 0; i < 5; i++) {
                int e = tid + i*256;
                pb[i] = g_wt[((d+1)*GBK + (e>>6))*NVZ + (e&63)];
            }
        }
        for (int f = tid; f < 640; f += 256) {
            int m = f & 63, t = f >> 6;
            float sv, cv;
            sincos_poly(dl[d][m] * fl[t], sv, cv);
            As[t][m]    = sv;
            As[t+10][m] = cv;
        }
        __syncthreads();
        #pragma unroll
        for (int kk = 0; kk < GBK; kk++) {
            float4 a = *(const float4*)&As[kk][ty*4];
            const u64* bp = (const u64*)&Bs[cur][kk][tx*4];
            u64 b01 = bp[0], b23 = bp[1];
            float av[4] = {a.x,a.y,a.z,a.w};
            #pragma unroll
            for (int i = 0; i < 4; i++) {
                u64 ai = pack2(av[i], av[i]);
                acc[i][0] = ffma2(ai, b01, acc[i][0]);
                acc[i][1] = ffma2(ai, b23, acc[i][1]);
            }
        }
        __syncthreads();
        if (d < NDIST-1) {
            #pragma unroll
            for (int i = 0; i < 5; i++) {
                int e = tid + i*256;
                Bs[cur^1][e>>6][e&63] = pb[i];
            }
        }
    }
    #pragma unroll
    for (int i = 0; i < 4; i++) {
        int m = m0 + ty*4 + i;
        float c0,c1,c2,c3;
        unpack2(acc[i][0], c0, c1);
        unpack2(acc[i][1], c2, c3);
        float* od = out + (size_t)m*(FZ+NVZ) + FZ + tx*4;
        od[0]=c0; od[1]=c1; od[2]=c2; od[3]=c3;
    }
}

extern "C" void kernel_launch(void* const* d_in, const int* in_sizes, int n_in,
                              void* d_out, int out_size) {
    const float* x    = (const float*)d_in[0];
    const float* aff  = (const float*)d_in[1];
    const float* nw   = (const float*)d_in[2];
    const float* lit  = (const float*)d_in[3];
    const void*  mask = d_in[4];
    float* out = (float*)d_out;

    detect_kernel<<<1, 256>>>((const unsigned int*)mask);
    wt_kernel<<<(NVZ*NFEAT + 255)/256, 256>>>(nw);
    setup_kernel<<<(NN+255)/256, 256>>>(aff, lit, mask, out);
    prefix_kernel<<<1, 1024>>>();
    scatter_kernel<<<(NN+255)/256, 256>>>();
    knn_kernel<<<NN/8, 256>>>(out);
    geom_kernel<<<NN, 32>>>(aff, out);
    gemm_kernel<<<NN/64, 256>>>(x, out);
}